// round 16
// baseline (speedup 1.0000x reference)
#include <cuda_runtime.h>
#include <cuda_bf16.h>
#include <cuda_fp16.h>
#include <math.h>
#include <stdint.h>

// ---------------------------------------------------------------------------
// TopoGCN: 5 x (GEMM -> SpMM -> bias+ReLU) + MLP head.
// HMMA fp16 split-A two-product GEMM: acc = Ah*Bh + Al*Bh.
// This round: true 2-deep cp.async prefetch (issue g+2 after barrier),
// SpMM 2 rows per 256-thread block.
// ---------------------------------------------------------------------------

#define HID 512
#define MAXN 10048
#define MAXE 160000

__device__ float   g_h[MAXN * HID];        // GEMM out (fp32)
__device__ __half  g_xh[MAXN * HID];       // activation hi (fp16)
__device__ __half  g_xl[MAXN * HID];       // activation lo (fp16)
__device__ __half  g_wh[6 * HID * HID];    // W^T (fp16) [n][k], 6 slots
__device__ int   g_cnt[MAXN];
__device__ int   g_off[MAXN + 1];
__device__ int   g_cur[MAXN];
__device__ int   g_scol[MAXE];
__device__ float g_sval[MAXE];

__device__ __forceinline__ uint32_t smem_u32(const void* p) {
    uint32_t a;
    asm("{ .reg .u64 t; cvta.to.shared.u64 t, %1; cvt.u32.u64 %0, t; }" : "=r"(a) : "l"(p));
    return a;
}

// ---------------------------------------------------------------------------
// HMMA GEMM: block 128x128, 8 warps (4m x 2n), warp tile 32x64, BK=32.
// Per k-chunk group: load {Ah, Al, Bh} once; Ah*Bh then Al*Bh (b live).
// 16 groups, mod-9 ring, one barrier per group, 2-deep prefetch:
//   slots(g+2) == slots(g-1) mod 9, and all warps passed compute(g-1)
//   before the barrier at iter g, so overwrite is safe.
// Smem rows padded to 80B (verified conflict-free ldmatrix).
// ---------------------------------------------------------------------------
#define BM 128
#define BN 128
#define BKC 32
#define RS 80
#define TILE_B (128 * RS)          // 10240 bytes per tile
#define NTILE 9
#define GSMEM (NTILE * TILE_B)     // 92160

#define LDM_X4(r, addr) \
    asm volatile("ldmatrix.sync.aligned.m8n8.x4.shared.b16 {%0,%1,%2,%3}, [%4];" \
                 : "=r"((r)[0]), "=r"((r)[1]), "=r"((r)[2]), "=r"((r)[3]) : "r"(addr))

#define MMA16816(c, a, b0, b1) \
    asm volatile("mma.sync.aligned.m16n8k16.row.col.f32.f16.f16.f32 " \
                 "{%0,%1,%2,%3}, {%4,%5,%6,%7}, {%8,%9}, {%0,%1,%2,%3};" \
                 : "+f"((c)[0]), "+f"((c)[1]), "+f"((c)[2]), "+f"((c)[3]) \
                 : "r"((a)[0]), "r"((a)[1]), "r"((a)[2]), "r"((a)[3]), "r"(b0), "r"(b1))

template <int MODE>  // 0 = plain store, 1 = bias + relu
__global__ __launch_bounds__(256, 2)
void gemm_hmma(const __half* __restrict__ Ah, const __half* __restrict__ Al,
               const __half* __restrict__ Bh,
               float* __restrict__ C, const float* __restrict__ bias, int M) {
    extern __shared__ __align__(16) char smem[];
    const uint32_t sb = smem_u32(smem);
    const int t = threadIdx.x;
    const int wid = t >> 5, lane = t & 31;
    const int m0 = blockIdx.y * BM, n0 = blockIdx.x * BN;
    const int wm = wid & 3, wn = wid >> 2;      // warp tile 32(m) x 64(n)

    float acc[2][8][4];
#pragma unroll
    for (int i = 0; i < 2; ++i)
#pragma unroll
        for (int j = 0; j < 8; ++j)
#pragma unroll
            for (int q = 0; q < 4; ++q) acc[i][j][q] = 0.0f;

    auto load_tile = [&](int slot, const __half* ptr, int k0, bool isA) {
        const uint32_t tb = sb + slot * TILE_B;
#pragma unroll
        for (int w = 0; w < 2; ++w) {
            int u = w * 256 + t;
            int row = u >> 2;
            int kc = (u & 3) * 8;
            uint32_t dst = tb + row * RS + kc * 2;
            const void* src = ptr + (size_t)((isA ? m0 : n0) + row) * HID + k0 + kc;
            int sz = (!isA || (m0 + row < M)) ? 16 : 0;
            asm volatile("cp.async.cg.shared.global [%0], [%1], 16, %2;"
                         :: "r"(dst), "l"(src), "r"(sz));
        }
    };

    auto issue_group = [&](int g) {
        const int k0 = g * BKC;
        load_tile((3 * g + 0) % NTILE, Ah, k0, true);
        load_tile((3 * g + 1) % NTILE, Al, k0, true);
        load_tile((3 * g + 2) % NTILE, Bh, k0, false);
        asm volatile("cp.async.commit_group;" ::: "memory");
    };

    auto lda = [&](uint32_t a[2][4], int slot, int ks) {
        const uint32_t tb = sb + slot * TILE_B;
#pragma unroll
        for (int i = 0; i < 2; ++i) {
            int row = wm * 32 + i * 16 + (lane & 15);
            LDM_X4(a[i], tb + row * RS + ks * 32 + ((lane >> 4) << 4));
        }
    };
    auto ldb = [&](uint32_t b[4][4], int slot, int ks) {
        const uint32_t tb = sb + slot * TILE_B;
        int q = lane >> 3, r = lane & 7;
#pragma unroll
        for (int j2 = 0; j2 < 4; ++j2) {
            int n = wn * 64 + j2 * 16 + ((q >> 1) << 3) + r;
            LDM_X4(b[j2], tb + n * RS + ks * 32 + ((q & 1) << 4));
        }
    };
    auto mma16 = [&](uint32_t a[2][4], uint32_t b[4][4]) {
#pragma unroll
        for (int i = 0; i < 2; ++i)
#pragma unroll
            for (int j = 0; j < 8; ++j) {
                const uint32_t* bb = b[j >> 1];
                if (j & 1) MMA16816(acc[i][j], a[i], bb[2], bb[3]);
                else       MMA16816(acc[i][j], a[i], bb[0], bb[1]);
            }
    };

    issue_group(0);
    issue_group(1);
    for (int g = 0; g < 16; ++g) {
        if (g < 15) {
            asm volatile("cp.async.wait_group 1;" ::: "memory");
        } else {
            asm volatile("cp.async.wait_group 0;" ::: "memory");
        }
        __syncthreads();
        if (g + 2 < 16) issue_group(g + 2);   // overwrites slots of g-1: safe post-barrier

        const int sAh = (3 * g + 0) % NTILE;
        const int sAl = (3 * g + 1) % NTILE;
        const int sB  = (3 * g + 2) % NTILE;
#pragma unroll
        for (int ks = 0; ks < 2; ++ks) {
            uint32_t a[2][4], b[4][4];
            ldb(b, sB, ks);
            lda(a, sAh, ks);
            mma16(a, b);           // Ah * Bh
            lda(a, sAl, ks);
            mma16(a, b);           // Al * Bh  (b stays live)
        }
    }

    // epilogue
#pragma unroll
    for (int i = 0; i < 2; ++i) {
        int rowA = m0 + wm * 32 + i * 16 + (lane >> 2);
        int rowB = rowA + 8;
#pragma unroll
        for (int j = 0; j < 8; ++j) {
            int col = n0 + wn * 64 + j * 8 + (lane & 3) * 2;
            float2 v0 = make_float2(acc[i][j][0], acc[i][j][1]);
            float2 v1 = make_float2(acc[i][j][2], acc[i][j][3]);
            if (MODE == 1) {
                float b0 = bias[col], b1 = bias[col + 1];
                v0.x = fmaxf(v0.x + b0, 0.f);  v0.y = fmaxf(v0.y + b1, 0.f);
                v1.x = fmaxf(v1.x + b0, 0.f);  v1.y = fmaxf(v1.y + b1, 0.f);
            }
            if (rowA < M) *reinterpret_cast<float2*>(&C[(size_t)rowA * HID + col]) = v0;
            if (rowB < M) *reinterpret_cast<float2*>(&C[(size_t)rowB * HID + col]) = v1;
        }
    }
}

// ---------------------------------------------------------------------------
// Weight transpose + fp16 round: g_wh[slot][n][k] = fp16(W[k][n])
// ---------------------------------------------------------------------------
__global__ void wconv(const float* __restrict__ Wg, const float* __restrict__ vw1) {
    __shared__ float ts[32][33];
    const int s = blockIdx.z;
    const float* src = (s < 5) ? Wg + (size_t)s * HID * HID : vw1;
    const int n0 = blockIdx.x * 32, k0 = blockIdx.y * 32;
#pragma unroll
    for (int i = 0; i < 32; i += 8) {
        int k = k0 + threadIdx.y + i;
        ts[threadIdx.y + i][threadIdx.x] = src[(size_t)k * HID + n0 + threadIdx.x];
    }
    __syncthreads();
    size_t sbase = (size_t)s * HID * HID;
#pragma unroll
    for (int i = 0; i < 32; i += 8) {
        int n = n0 + threadIdx.y + i;
        float v = ts[threadIdx.x][threadIdx.y + i];  // = W[k0+tx][n]
        g_wh[sbase + (size_t)n * HID + k0 + threadIdx.x] = __float2half_rn(v);
    }
}

// ---------------------------------------------------------------------------
// Activation split for feat: xh = fp16(x), xl = fp16(x - float(xh))
// ---------------------------------------------------------------------------
__global__ void conv_act(const float* __restrict__ src, int n4) {
    int i = blockIdx.x * blockDim.x + threadIdx.x;
    if (i >= n4) return;
    float4 v = reinterpret_cast<const float4*>(src)[i];
    __half h0 = __float2half_rn(v.x), h1 = __float2half_rn(v.y);
    __half h2 = __float2half_rn(v.z), h3 = __float2half_rn(v.w);
    __half l0 = __float2half_rn(v.x - __half2float(h0));
    __half l1 = __float2half_rn(v.y - __half2float(h1));
    __half l2 = __float2half_rn(v.z - __half2float(h2));
    __half l3 = __float2half_rn(v.w - __half2float(h3));
    ushort4 hv = make_ushort4(__half_as_ushort(h0), __half_as_ushort(h1),
                              __half_as_ushort(h2), __half_as_ushort(h3));
    ushort4 lv = make_ushort4(__half_as_ushort(l0), __half_as_ushort(l1),
                              __half_as_ushort(l2), __half_as_ushort(l3));
    *reinterpret_cast<ushort4*>(&g_xh[i * 4]) = hv;
    *reinterpret_cast<ushort4*>(&g_xl[i * 4]) = lv;
}

// ---------------------------------------------------------------------------
// CSR build (once per launch)
// ---------------------------------------------------------------------------
__global__ void csr_zero(int n) {
    int i = blockIdx.x * blockDim.x + threadIdx.x;
    if (i < n) g_cnt[i] = 0;
}
__global__ void csr_hist(const int* __restrict__ row, int E) {
    int e = blockIdx.x * blockDim.x + threadIdx.x;
    if (e < E) atomicAdd(&g_cnt[row[e]], 1);
}
__global__ __launch_bounds__(1024)
void csr_scan(int n) {
    __shared__ int warp_sums[32];
    const int t = threadIdx.x;
    const int per = (n + 1023) / 1024;
    const int base = t * per;
    int local[16];
    int sum = 0;
#pragma unroll 4
    for (int i = 0; i < per; ++i) {
        int idx = base + i;
        int v = (idx < n) ? g_cnt[idx] : 0;
        local[i] = sum;
        sum += v;
    }
    const int lane = t & 31, wid = t >> 5;
    int s = sum;
#pragma unroll
    for (int o = 1; o < 32; o <<= 1) {
        int u = __shfl_up_sync(0xffffffffu, s, o);
        if (lane >= o) s += u;
    }
    if (lane == 31) warp_sums[wid] = s;
    __syncthreads();
    if (wid == 0) {
        int ws = warp_sums[lane];
#pragma unroll
        for (int o = 1; o < 32; o <<= 1) {
            int u = __shfl_up_sync(0xffffffffu, ws, o);
            if (lane >= o) ws += u;
        }
        warp_sums[lane] = ws;
    }
    __syncthreads();
    int excl = (s - sum) + (wid > 0 ? warp_sums[wid - 1] : 0);
#pragma unroll 4
    for (int i = 0; i < per; ++i) {
        int idx = base + i;
        if (idx < n) {
            int off = excl + local[i];
            g_off[idx] = off;
            g_cur[idx] = off;
        }
    }
    if (t == 1023) g_off[n] = excl + sum;
}
__global__ void csr_scatter(const int* __restrict__ row, const int* __restrict__ col,
                            const float* __restrict__ val, int E) {
    int e = blockIdx.x * blockDim.x + threadIdx.x;
    if (e >= E) return;
    int r = row[e];
    int slot = atomicAdd(&g_cur[r], 1);
    g_scol[slot] = col[e];
    g_sval[slot] = val[e];
}

// ---------------------------------------------------------------------------
// SpMM gather + bias + ReLU + fp16 split. 8-edge unroll.
// 2 rows per 256-thread block: threads [0,128) row 2b, [128,256) row 2b+1.
// ---------------------------------------------------------------------------
__global__ __launch_bounds__(256)
void spmm_gather(const float* __restrict__ bias, int M) {
    const int r = blockIdx.x * 2 + (threadIdx.x >> 7);
    if (r >= M) return;
    const int t = threadIdx.x & 127;
    const int beg = g_off[r];
    const int end = g_off[r + 1];
    const int c4 = t * 4;

    float4 acc[4];
#pragma unroll
    for (int q = 0; q < 4; ++q) acc[q] = make_float4(0.f, 0.f, 0.f, 0.f);

    int j = beg;
    for (; j + 7 < end; j += 8) {
        int   cc[8];
        float vv[8];
        float4 hh[8];
#pragma unroll
        for (int u = 0; u < 8; ++u) { cc[u] = g_scol[j + u]; vv[u] = g_sval[j + u]; }
#pragma unroll
        for (int u = 0; u < 8; ++u)
            hh[u] = *reinterpret_cast<const float4*>(&g_h[(size_t)cc[u] * HID + c4]);
#pragma unroll
        for (int u = 0; u < 8; ++u) {
            float4& a = acc[u & 3];
            a.x = fmaf(vv[u], hh[u].x, a.x);  a.y = fmaf(vv[u], hh[u].y, a.y);
            a.z = fmaf(vv[u], hh[u].z, a.z);  a.w = fmaf(vv[u], hh[u].w, a.w);
        }
    }
    for (; j < end; ++j) {
        int   c0 = g_scol[j];
        float v0 = g_sval[j];
        float4 h0 = *reinterpret_cast<const float4*>(&g_h[(size_t)c0 * HID + c4]);
        acc[0].x = fmaf(v0, h0.x, acc[0].x);  acc[0].y = fmaf(v0, h0.y, acc[0].y);
        acc[0].z = fmaf(v0, h0.z, acc[0].z);  acc[0].w = fmaf(v0, h0.w, acc[0].w);
    }

    float4 b = *reinterpret_cast<const float4*>(&bias[c4]);
    float ox = fmaxf((acc[0].x + acc[1].x) + (acc[2].x + acc[3].x) + b.x, 0.f);
    float oy = fmaxf((acc[0].y + acc[1].y) + (acc[2].y + acc[3].y) + b.y, 0.f);
    float oz = fmaxf((acc[0].z + acc[1].z) + (acc[2].z + acc[3].z) + b.z, 0.f);
    float ow = fmaxf((acc[0].w + acc[1].w) + (acc[2].w + acc[3].w) + b.w, 0.f);

    __half h0 = __float2half_rn(ox), h1 = __float2half_rn(oy);
    __half h2 = __float2half_rn(oz), h3 = __float2half_rn(ow);
    __half l0 = __float2half_rn(ox - __half2float(h0));
    __half l1 = __float2half_rn(oy - __half2float(h1));
    __half l2 = __float2half_rn(oz - __half2float(h2));
    __half l3 = __float2half_rn(ow - __half2float(h3));
    ushort4 hv = make_ushort4(__half_as_ushort(h0), __half_as_ushort(h1),
                              __half_as_ushort(h2), __half_as_ushort(h3));
    ushort4 lv = make_ushort4(__half_as_ushort(l0), __half_as_ushort(l1),
                              __half_as_ushort(l2), __half_as_ushort(l3));
    *reinterpret_cast<ushort4*>(&g_xh[(size_t)r * HID + c4]) = hv;
    *reinterpret_cast<ushort4*>(&g_xl[(size_t)r * HID + c4]) = lv;
}

// ---------------------------------------------------------------------------
// head2
// ---------------------------------------------------------------------------
__global__ void head2(const float* __restrict__ w, const float* __restrict__ b,
                      float* __restrict__ out, int M) {
    int warp = (blockIdx.x * blockDim.x + threadIdx.x) >> 5;
    int lane = threadIdx.x & 31;
    if (warp >= M) return;
    const float* hr = &g_h[(size_t)warp * HID];
    float s = 0.f;
#pragma unroll
    for (int k = lane * 4; k < HID; k += 32 * 4) {
        float4 hv = *reinterpret_cast<const float4*>(&hr[k]);
        float4 wv = *reinterpret_cast<const float4*>(&w[k]);
        s = fmaf(hv.x, wv.x, s);
        s = fmaf(hv.y, wv.y, s);
        s = fmaf(hv.z, wv.z, s);
        s = fmaf(hv.w, wv.w, s);
    }
#pragma unroll
    for (int off = 16; off > 0; off >>= 1)
        s += __shfl_down_sync(0xffffffffu, s, off);
    if (lane == 0) {
        float z = s + b[0];
        out[warp] = 1.0f / (1.0f + expf(-z));
    }
}

// ---------------------------------------------------------------------------
// launch
// ---------------------------------------------------------------------------
extern "C" void kernel_launch(void* const* d_in, const int* in_sizes, int n_in,
                              void* d_out, int out_size) {
    const float* feat    = (const float*)d_in[0];
    const int*   adj_row = (const int*)d_in[1];
    const int*   adj_col = (const int*)d_in[2];
    const float* adj_val = (const float*)d_in[3];
    const float* Wg      = (const float*)d_in[4];
    const float* bg      = (const float*)d_in[5];
    const float* vw1     = (const float*)d_in[6];
    const float* vb1     = (const float*)d_in[7];
    const float* vw2     = (const float*)d_in[8];
    const float* vb2     = (const float*)d_in[9];
    float*       out     = (float*)d_out;

    const int M = in_sizes[0] / HID;   // 10000
    const int E = in_sizes[1];         // 160000
    const int n4 = (M * HID) / 4;

    float*   h_ptr;  cudaGetSymbolAddress((void**)&h_ptr,  g_h);
    __half*  xh_ptr; cudaGetSymbolAddress((void**)&xh_ptr, g_xh);
    __half*  xl_ptr; cudaGetSymbolAddress((void**)&xl_ptr, g_xl);
    __half*  wh_ptr; cudaGetSymbolAddress((void**)&wh_ptr, g_wh);

    cudaFuncSetAttribute(gemm_hmma<0>, cudaFuncAttributeMaxDynamicSharedMemorySize, GSMEM);
    cudaFuncSetAttribute(gemm_hmma<1>, cudaFuncAttributeMaxDynamicSharedMemorySize, GSMEM);

    // --- CSR build + weight/feat conversion ---
    csr_zero<<<(M + 255) / 256, 256>>>(M);
    csr_hist<<<(E + 255) / 256, 256>>>(adj_row, E);
    csr_scan<<<1, 1024>>>(M);
    csr_scatter<<<(E + 255) / 256, 256>>>(adj_row, adj_col, adj_val, E);
    wconv<<<dim3(HID / 32, HID / 32, 6), dim3(32, 8)>>>(Wg, vw1);
    conv_act<<<(n4 + 255) / 256, 256>>>(feat, n4);

    const int mb = (M + BM - 1) / BM;   // 79
    dim3 gGrid(HID / BN, mb);           // (4, 79)

    for (int layer = 0; layer < 5; ++layer) {
        gemm_hmma<0><<<gGrid, 256, GSMEM>>>(xh_ptr, xl_ptr,
                                            wh_ptr + (size_t)layer * HID * HID,
                                            h_ptr, nullptr, M);
        spmm_gather<<<(M + 1) / 2, 256>>>(bg + (size_t)layer * HID, M);
    }

    // h = relu(x @ vw1 + vb1)
    gemm_hmma<1><<<gGrid, 256, GSMEM>>>(xh_ptr, xl_ptr,
                                        wh_ptr + (size_t)5 * HID * HID,
                                        h_ptr, vb1, M);
    // out = sigmoid(h @ vw2 + vb2)
    head2<<<(M * 32 + 255) / 256, 256>>>(vw2, vb2, out, M);
}

// round 17
// speedup vs baseline: 1.0861x; 1.0861x over previous
#include <cuda_runtime.h>
#include <cuda_bf16.h>
#include <cuda_fp16.h>
#include <math.h>
#include <stdint.h>

// ---------------------------------------------------------------------------
// TopoGCN: 5 x (GEMM -> SpMM -> bias+ReLU) + MLP head.
// HMMA fp16 split-A two-product GEMM (R14 proven schedule), CSR gather SpMM.
// This round: MODE-1 GEMM fuses bias+ReLU+dot(vw2) into the epilogue
// (per-row atomic partials), removing the 40MB h round-trip and head2.
// ---------------------------------------------------------------------------

#define HID 512
#define MAXN 10048
#define MAXE 160000

__device__ float   g_h[MAXN * HID];        // GEMM out (fp32)
__device__ float   g_ps[MAXN];             // fused-head per-row partial sums
__device__ __half  g_xh[MAXN * HID];       // activation hi (fp16)
__device__ __half  g_xl[MAXN * HID];       // activation lo (fp16)
__device__ __half  g_wh[6 * HID * HID];    // W^T (fp16) [n][k], 6 slots
__device__ int   g_cnt[MAXN];
__device__ int   g_off[MAXN + 1];
__device__ int   g_cur[MAXN];
__device__ int   g_scol[MAXE];
__device__ float g_sval[MAXE];

__device__ __forceinline__ uint32_t smem_u32(const void* p) {
    uint32_t a;
    asm("{ .reg .u64 t; cvta.to.shared.u64 t, %1; cvt.u32.u64 %0, t; }" : "=r"(a) : "l"(p));
    return a;
}

// ---------------------------------------------------------------------------
// HMMA GEMM: block 128x128, 8 warps (4m x 2n), warp tile 32x64, BK=32.
// Per k-chunk group: load {Ah, Al, Bh} once; Ah*Bh then Al*Bh (b live).
// 16 groups, mod-9 ring, R14 schedule (issue g+1 before wait(1)).
// Smem rows padded to 80B (verified conflict-free ldmatrix).
// ---------------------------------------------------------------------------
#define BM 128
#define BN 128
#define BKC 32
#define RS 80
#define TILE_B (128 * RS)          // 10240 bytes per tile
#define NTILE 9
#define GSMEM (NTILE * TILE_B)     // 92160

#define LDM_X4(r, addr) \
    asm volatile("ldmatrix.sync.aligned.m8n8.x4.shared.b16 {%0,%1,%2,%3}, [%4];" \
                 : "=r"((r)[0]), "=r"((r)[1]), "=r"((r)[2]), "=r"((r)[3]) : "r"(addr))

#define MMA16816(c, a, b0, b1) \
    asm volatile("mma.sync.aligned.m16n8k16.row.col.f32.f16.f16.f32 " \
                 "{%0,%1,%2,%3}, {%4,%5,%6,%7}, {%8,%9}, {%0,%1,%2,%3};" \
                 : "+f"((c)[0]), "+f"((c)[1]), "+f"((c)[2]), "+f"((c)[3]) \
                 : "r"((a)[0]), "r"((a)[1]), "r"((a)[2]), "r"((a)[3]), "r"(b0), "r"(b1))

template <int MODE>  // 0 = plain fp32 store to C, 1 = fused bias+relu+dot(vw2)
__global__ __launch_bounds__(256, 2)
void gemm_hmma(const __half* __restrict__ Ah, const __half* __restrict__ Al,
               const __half* __restrict__ Bh,
               float* __restrict__ C, const float* __restrict__ bias,
               const float* __restrict__ Wv2, int M) {
    extern __shared__ __align__(16) char smem[];
    const uint32_t sb = smem_u32(smem);
    const int t = threadIdx.x;
    const int wid = t >> 5, lane = t & 31;
    const int m0 = blockIdx.y * BM, n0 = blockIdx.x * BN;
    const int wm = wid & 3, wn = wid >> 2;      // warp tile 32(m) x 64(n)

    float acc[2][8][4];
#pragma unroll
    for (int i = 0; i < 2; ++i)
#pragma unroll
        for (int j = 0; j < 8; ++j)
#pragma unroll
            for (int q = 0; q < 4; ++q) acc[i][j][q] = 0.0f;

    auto load_tile = [&](int slot, const __half* ptr, int k0, bool isA) {
        const uint32_t tb = sb + slot * TILE_B;
#pragma unroll
        for (int w = 0; w < 2; ++w) {
            int u = w * 256 + t;
            int row = u >> 2;
            int kc = (u & 3) * 8;
            uint32_t dst = tb + row * RS + kc * 2;
            const void* src = ptr + (size_t)((isA ? m0 : n0) + row) * HID + k0 + kc;
            int sz = (!isA || (m0 + row < M)) ? 16 : 0;
            asm volatile("cp.async.cg.shared.global [%0], [%1], 16, %2;"
                         :: "r"(dst), "l"(src), "r"(sz));
        }
    };

    auto issue_group = [&](int g) {
        const int k0 = g * BKC;
        load_tile((3 * g + 0) % NTILE, Ah, k0, true);
        load_tile((3 * g + 1) % NTILE, Al, k0, true);
        load_tile((3 * g + 2) % NTILE, Bh, k0, false);
        asm volatile("cp.async.commit_group;" ::: "memory");
    };

    auto lda = [&](uint32_t a[2][4], int slot, int ks) {
        const uint32_t tb = sb + slot * TILE_B;
#pragma unroll
        for (int i = 0; i < 2; ++i) {
            int row = wm * 32 + i * 16 + (lane & 15);
            LDM_X4(a[i], tb + row * RS + ks * 32 + ((lane >> 4) << 4));
        }
    };
    auto ldb = [&](uint32_t b[4][4], int slot, int ks) {
        const uint32_t tb = sb + slot * TILE_B;
        int q = lane >> 3, r = lane & 7;
#pragma unroll
        for (int j2 = 0; j2 < 4; ++j2) {
            int n = wn * 64 + j2 * 16 + ((q >> 1) << 3) + r;
            LDM_X4(b[j2], tb + n * RS + ks * 32 + ((q & 1) << 4));
        }
    };
    auto mma16 = [&](uint32_t a[2][4], uint32_t b[4][4]) {
#pragma unroll
        for (int i = 0; i < 2; ++i)
#pragma unroll
            for (int j = 0; j < 8; ++j) {
                const uint32_t* bb = b[j >> 1];
                if (j & 1) MMA16816(acc[i][j], a[i], bb[2], bb[3]);
                else       MMA16816(acc[i][j], a[i], bb[0], bb[1]);
            }
    };

    issue_group(0);
    for (int g = 0; g < 16; ++g) {
        if (g + 1 < 16) {
            issue_group(g + 1);
            asm volatile("cp.async.wait_group 1;" ::: "memory");
        } else {
            asm volatile("cp.async.wait_group 0;" ::: "memory");
        }
        __syncthreads();

        const int sAh = (3 * g + 0) % NTILE;
        const int sAl = (3 * g + 1) % NTILE;
        const int sB  = (3 * g + 2) % NTILE;
#pragma unroll
        for (int ks = 0; ks < 2; ++ks) {
            uint32_t a[2][4], b[4][4];
            ldb(b, sB, ks);
            lda(a, sAh, ks);
            mma16(a, b);           // Ah * Bh
            lda(a, sAl, ks);
            mma16(a, b);           // Al * Bh  (b stays live)
        }
    }

    // epilogue
#pragma unroll
    for (int i = 0; i < 2; ++i) {
        int rowA = m0 + wm * 32 + i * 16 + (lane >> 2);
        int rowB = rowA + 8;
        if (MODE == 0) {
#pragma unroll
            for (int j = 0; j < 8; ++j) {
                int col = n0 + wn * 64 + j * 8 + (lane & 3) * 2;
                float2 v0 = make_float2(acc[i][j][0], acc[i][j][1]);
                float2 v1 = make_float2(acc[i][j][2], acc[i][j][3]);
                if (rowA < M) *reinterpret_cast<float2*>(&C[(size_t)rowA * HID + col]) = v0;
                if (rowB < M) *reinterpret_cast<float2*>(&C[(size_t)rowB * HID + col]) = v1;
            }
        } else {
            // fused: p = sum_col relu(acc + bias[col]) * vw2[col]
            float pA = 0.f, pB = 0.f;
#pragma unroll
            for (int j = 0; j < 8; ++j) {
                int col = n0 + wn * 64 + j * 8 + (lane & 3) * 2;
                float b0 = bias[col], b1 = bias[col + 1];
                float w0 = Wv2[col],  w1 = Wv2[col + 1];
                pA = fmaf(fmaxf(acc[i][j][0] + b0, 0.f), w0, pA);
                pA = fmaf(fmaxf(acc[i][j][1] + b1, 0.f), w1, pA);
                pB = fmaf(fmaxf(acc[i][j][2] + b0, 0.f), w0, pB);
                pB = fmaf(fmaxf(acc[i][j][3] + b1, 0.f), w1, pB);
            }
            // reduce over the 4 lanes (lane&3) sharing each row
            pA += __shfl_xor_sync(0xffffffffu, pA, 1);
            pA += __shfl_xor_sync(0xffffffffu, pA, 2);
            pB += __shfl_xor_sync(0xffffffffu, pB, 1);
            pB += __shfl_xor_sync(0xffffffffu, pB, 2);
            if ((lane & 3) == 0) {
                if (rowA < M) atomicAdd(&g_ps[rowA], pA);
                if (rowB < M) atomicAdd(&g_ps[rowB], pB);
            }
        }
    }
}

// ---------------------------------------------------------------------------
// Weight transpose + fp16 round: g_wh[slot][n][k] = fp16(W[k][n])
// ---------------------------------------------------------------------------
__global__ void wconv(const float* __restrict__ Wg, const float* __restrict__ vw1) {
    __shared__ float ts[32][33];
    const int s = blockIdx.z;
    const float* src = (s < 5) ? Wg + (size_t)s * HID * HID : vw1;
    const int n0 = blockIdx.x * 32, k0 = blockIdx.y * 32;
#pragma unroll
    for (int i = 0; i < 32; i += 8) {
        int k = k0 + threadIdx.y + i;
        ts[threadIdx.y + i][threadIdx.x] = src[(size_t)k * HID + n0 + threadIdx.x];
    }
    __syncthreads();
    size_t sbase = (size_t)s * HID * HID;
#pragma unroll
    for (int i = 0; i < 32; i += 8) {
        int n = n0 + threadIdx.y + i;
        float v = ts[threadIdx.x][threadIdx.y + i];  // = W[k0+tx][n]
        g_wh[sbase + (size_t)n * HID + k0 + threadIdx.x] = __float2half_rn(v);
    }
}

// ---------------------------------------------------------------------------
// Activation split for feat: xh = fp16(x), xl = fp16(x - float(xh))
// ---------------------------------------------------------------------------
__global__ void conv_act(const float* __restrict__ src, int n4) {
    int i = blockIdx.x * blockDim.x + threadIdx.x;
    if (i >= n4) return;
    float4 v = reinterpret_cast<const float4*>(src)[i];
    __half h0 = __float2half_rn(v.x), h1 = __float2half_rn(v.y);
    __half h2 = __float2half_rn(v.z), h3 = __float2half_rn(v.w);
    __half l0 = __float2half_rn(v.x - __half2float(h0));
    __half l1 = __float2half_rn(v.y - __half2float(h1));
    __half l2 = __float2half_rn(v.z - __half2float(h2));
    __half l3 = __float2half_rn(v.w - __half2float(h3));
    ushort4 hv = make_ushort4(__half_as_ushort(h0), __half_as_ushort(h1),
                              __half_as_ushort(h2), __half_as_ushort(h3));
    ushort4 lv = make_ushort4(__half_as_ushort(l0), __half_as_ushort(l1),
                              __half_as_ushort(l2), __half_as_ushort(l3));
    *reinterpret_cast<ushort4*>(&g_xh[i * 4]) = hv;
    *reinterpret_cast<ushort4*>(&g_xl[i * 4]) = lv;
}

// ---------------------------------------------------------------------------
// CSR build (once per launch). csr_zero also zeros the fused-head partials.
// ---------------------------------------------------------------------------
__global__ void csr_zero(int n) {
    int i = blockIdx.x * blockDim.x + threadIdx.x;
    if (i < n) { g_cnt[i] = 0; g_ps[i] = 0.0f; }
}
__global__ void csr_hist(const int* __restrict__ row, int E) {
    int e = blockIdx.x * blockDim.x + threadIdx.x;
    if (e < E) atomicAdd(&g_cnt[row[e]], 1);
}
__global__ __launch_bounds__(1024)
void csr_scan(int n) {
    __shared__ int warp_sums[32];
    const int t = threadIdx.x;
    const int per = (n + 1023) / 1024;
    const int base = t * per;
    int local[16];
    int sum = 0;
#pragma unroll 4
    for (int i = 0; i < per; ++i) {
        int idx = base + i;
        int v = (idx < n) ? g_cnt[idx] : 0;
        local[i] = sum;
        sum += v;
    }
    const int lane = t & 31, wid = t >> 5;
    int s = sum;
#pragma unroll
    for (int o = 1; o < 32; o <<= 1) {
        int u = __shfl_up_sync(0xffffffffu, s, o);
        if (lane >= o) s += u;
    }
    if (lane == 31) warp_sums[wid] = s;
    __syncthreads();
    if (wid == 0) {
        int ws = warp_sums[lane];
#pragma unroll
        for (int o = 1; o < 32; o <<= 1) {
            int u = __shfl_up_sync(0xffffffffu, ws, o);
            if (lane >= o) ws += u;
        }
        warp_sums[lane] = ws;
    }
    __syncthreads();
    int excl = (s - sum) + (wid > 0 ? warp_sums[wid - 1] : 0);
#pragma unroll 4
    for (int i = 0; i < per; ++i) {
        int idx = base + i;
        if (idx < n) {
            int off = excl + local[i];
            g_off[idx] = off;
            g_cur[idx] = off;
        }
    }
    if (t == 1023) g_off[n] = excl + sum;
}
__global__ void csr_scatter(const int* __restrict__ row, const int* __restrict__ col,
                            const float* __restrict__ val, int E) {
    int e = blockIdx.x * blockDim.x + threadIdx.x;
    if (e >= E) return;
    int r = row[e];
    int slot = atomicAdd(&g_cur[r], 1);
    g_scol[slot] = col[e];
    g_sval[slot] = val[e];
}

// ---------------------------------------------------------------------------
// SpMM gather + bias + ReLU + fp16 split. 8-edge unroll. (R14 proven config)
// ---------------------------------------------------------------------------
__global__ __launch_bounds__(128)
void spmm_gather(const float* __restrict__ bias) {
    const int r = blockIdx.x;
    const int t = threadIdx.x;
    const int beg = g_off[r];
    const int end = g_off[r + 1];
    const int c4 = t * 4;

    float4 acc[4];
#pragma unroll
    for (int q = 0; q < 4; ++q) acc[q] = make_float4(0.f, 0.f, 0.f, 0.f);

    int j = beg;
    for (; j + 7 < end; j += 8) {
        int   cc[8];
        float vv[8];
        float4 hh[8];
#pragma unroll
        for (int u = 0; u < 8; ++u) { cc[u] = g_scol[j + u]; vv[u] = g_sval[j + u]; }
#pragma unroll
        for (int u = 0; u < 8; ++u)
            hh[u] = *reinterpret_cast<const float4*>(&g_h[(size_t)cc[u] * HID + c4]);
#pragma unroll
        for (int u = 0; u < 8; ++u) {
            float4& a = acc[u & 3];
            a.x = fmaf(vv[u], hh[u].x, a.x);  a.y = fmaf(vv[u], hh[u].y, a.y);
            a.z = fmaf(vv[u], hh[u].z, a.z);  a.w = fmaf(vv[u], hh[u].w, a.w);
        }
    }
    for (; j < end; ++j) {
        int   c0 = g_scol[j];
        float v0 = g_sval[j];
        float4 h0 = *reinterpret_cast<const float4*>(&g_h[(size_t)c0 * HID + c4]);
        acc[0].x = fmaf(v0, h0.x, acc[0].x);  acc[0].y = fmaf(v0, h0.y, acc[0].y);
        acc[0].z = fmaf(v0, h0.z, acc[0].z);  acc[0].w = fmaf(v0, h0.w, acc[0].w);
    }

    float4 b = *reinterpret_cast<const float4*>(&bias[c4]);
    float ox = fmaxf((acc[0].x + acc[1].x) + (acc[2].x + acc[3].x) + b.x, 0.f);
    float oy = fmaxf((acc[0].y + acc[1].y) + (acc[2].y + acc[3].y) + b.y, 0.f);
    float oz = fmaxf((acc[0].z + acc[1].z) + (acc[2].z + acc[3].z) + b.z, 0.f);
    float ow = fmaxf((acc[0].w + acc[1].w) + (acc[2].w + acc[3].w) + b.w, 0.f);

    __half h0 = __float2half_rn(ox), h1 = __float2half_rn(oy);
    __half h2 = __float2half_rn(oz), h3 = __float2half_rn(ow);
    __half l0 = __float2half_rn(ox - __half2float(h0));
    __half l1 = __float2half_rn(oy - __half2float(h1));
    __half l2 = __float2half_rn(oz - __half2float(h2));
    __half l3 = __float2half_rn(ow - __half2float(h3));
    ushort4 hv = make_ushort4(__half_as_ushort(h0), __half_as_ushort(h1),
                              __half_as_ushort(h2), __half_as_ushort(h3));
    ushort4 lv = make_ushort4(__half_as_ushort(l0), __half_as_ushort(l1),
                              __half_as_ushort(l2), __half_as_ushort(l3));
    *reinterpret_cast<ushort4*>(&g_xh[(size_t)r * HID + c4]) = hv;
    *reinterpret_cast<ushort4*>(&g_xl[(size_t)r * HID + c4]) = lv;
}

// ---------------------------------------------------------------------------
// head_sig: out[r] = sigmoid(g_ps[r] + vb2[0])
// ---------------------------------------------------------------------------
__global__ void head_sig(const float* __restrict__ b, float* __restrict__ out, int M) {
    int i = blockIdx.x * blockDim.x + threadIdx.x;
    if (i < M) out[i] = 1.0f / (1.0f + expf(-(g_ps[i] + b[0])));
}

// ---------------------------------------------------------------------------
// launch
// ---------------------------------------------------------------------------
extern "C" void kernel_launch(void* const* d_in, const int* in_sizes, int n_in,
                              void* d_out, int out_size) {
    const float* feat    = (const float*)d_in[0];
    const int*   adj_row = (const int*)d_in[1];
    const int*   adj_col = (const int*)d_in[2];
    const float* adj_val = (const float*)d_in[3];
    const float* Wg      = (const float*)d_in[4];
    const float* bg      = (const float*)d_in[5];
    const float* vw1     = (const float*)d_in[6];
    const float* vb1     = (const float*)d_in[7];
    const float* vw2     = (const float*)d_in[8];
    const float* vb2     = (const float*)d_in[9];
    float*       out     = (float*)d_out;

    const int M = in_sizes[0] / HID;   // 10000
    const int E = in_sizes[1];         // 160000
    const int n4 = (M * HID) / 4;

    float*   h_ptr;  cudaGetSymbolAddress((void**)&h_ptr,  g_h);
    __half*  xh_ptr; cudaGetSymbolAddress((void**)&xh_ptr, g_xh);
    __half*  xl_ptr; cudaGetSymbolAddress((void**)&xl_ptr, g_xl);
    __half*  wh_ptr; cudaGetSymbolAddress((void**)&wh_ptr, g_wh);

    cudaFuncSetAttribute(gemm_hmma<0>, cudaFuncAttributeMaxDynamicSharedMemorySize, GSMEM);
    cudaFuncSetAttribute(gemm_hmma<1>, cudaFuncAttributeMaxDynamicSharedMemorySize, GSMEM);

    // --- CSR build + weight/feat conversion (also zeros g_ps) ---
    csr_zero<<<(M + 255) / 256, 256>>>(M);
    csr_hist<<<(E + 255) / 256, 256>>>(adj_row, E);
    csr_scan<<<1, 1024>>>(M);
    csr_scatter<<<(E + 255) / 256, 256>>>(adj_row, adj_col, adj_val, E);
    wconv<<<dim3(HID / 32, HID / 32, 6), dim3(32, 8)>>>(Wg, vw1);
    conv_act<<<(n4 + 255) / 256, 256>>>(feat, n4);

    const int mb = (M + BM - 1) / BM;   // 79
    dim3 gGrid(HID / BN, mb);           // (4, 79)

    for (int layer = 0; layer < 5; ++layer) {
        gemm_hmma<0><<<gGrid, 256, GSMEM>>>(xh_ptr, xl_ptr,
                                            wh_ptr + (size_t)layer * HID * HID,
                                            h_ptr, nullptr, nullptr, M);
        spmm_gather<<<M, 128>>>(bg + (size_t)layer * HID);
    }

    // fused: partials of sigmoid-input = sum relu(x@vw1+vb1)*vw2, via atomics
    gemm_hmma<1><<<gGrid, 256, GSMEM>>>(xh_ptr, xl_ptr,
                                        wh_ptr + (size_t)5 * HID * HID,
                                        nullptr, vb1, vw2, M);
    // out = sigmoid(partials + vb2)
    head_sig<<<(M + 255) / 256, 256>>>(vb2, out, M);
}